// round 3
// baseline (speedup 1.0000x reference)
#include <cuda_runtime.h>
#include <cuda_bf16.h>
#include <cstdint>

// Problem constants (fixed shapes)
#define BB   64
#define TT   256
#define VV   10000
#define EE   100
#define HH   128
#define GG   512          // 4H
#define BT   (BB*TT)      // 16384

#define LOGITS_ELEMS ((size_t)BT * VV)          // 163,840,000
#define HF_OFF  LOGITS_ELEMS
#define CF_OFF  (LOGITS_ELEMS + (size_t)BB*HH)
#define FULL_OUT (LOGITS_ELEMS + 2ull*BB*HH)

// Scratch (device globals; allocation-free per harness rules)
__device__ float g_xproj[(size_t)BT * GG];   // 33.5 MB  [b][t][g]
__device__ float g_hs[(size_t)BT * HH];      // 8.4 MB   [b][t][h]

// ---------------------------------------------------------------------------
// Kernel 1: embedding gather + input projection
// x_proj[bt][g] = sum_e emb[x[bt]][e] * W_ih[g][e] + b_ih[g] + b_hh[g]
// grid: BT/16 blocks, 512 threads (one per gate row g)
// ---------------------------------------------------------------------------
__global__ __launch_bounds__(512) void k_embed_proj(
    const int* __restrict__ x, const float* __restrict__ emb,
    const float* __restrict__ W_ih, const float* __restrict__ b_ih,
    const float* __restrict__ b_hh)
{
    __shared__ float xe_s[16 * EE];
    __shared__ int   toks[16];
    const int bt0 = blockIdx.x * 16;
    const int tid = threadIdx.x;

    if (tid < 16) toks[tid] = x[bt0 + tid];
    __syncthreads();
    for (int i = tid; i < 16 * EE; i += 512) {
        int r = i / EE, e = i - r * EE;
        xe_s[i] = emb[(size_t)toks[r] * EE + e];
    }
    __syncthreads();

    const int g = tid;
    float acc[16];
#pragma unroll
    for (int r = 0; r < 16; r++) acc[r] = 0.f;

    const float4* W4 = reinterpret_cast<const float4*>(W_ih + (size_t)g * EE);
#pragma unroll 5
    for (int e4 = 0; e4 < EE / 4; e4++) {
        float4 w = W4[e4];
#pragma unroll
        for (int r = 0; r < 16; r++) {
            float4 v = reinterpret_cast<const float4*>(xe_s + r * EE)[e4];
            acc[r] += w.x * v.x;
            acc[r] += w.y * v.y;
            acc[r] += w.z * v.z;
            acc[r] += w.w * v.w;
        }
    }
    const float bias = b_ih[g] + b_hh[g];
#pragma unroll
    for (int r = 0; r < 16; r++)
        g_xproj[(size_t)(bt0 + r) * GG + g] = acc[r] + bias;
}

// ---------------------------------------------------------------------------
// Kernel 2: LSTM recurrence. One block per batch element, 512 threads
// (one per gate row). W_hh k=0..63 in registers, k=64..127 in SMEM
// (transposed [k][g] for conflict-free LDS). c in registers of threads<128.
// ---------------------------------------------------------------------------
#define KREG  64
#define KSMEM 64
#define SMEM2_BYTES ((KSMEM*GG + HH + GG) * 4)

__device__ __forceinline__ float sigmoidf_(float v) {
    return 1.f / (1.f + expf(-v));
}

__global__ __launch_bounds__(512, 1) void k_lstm(
    const float* __restrict__ W_hh, float* __restrict__ out, long long out_size)
{
    extern __shared__ float smem2[];
    float* Wt_s    = smem2;                 // [KSMEM][512]
    float* h_s     = smem2 + KSMEM * GG;    // [128]
    float* gates_s = h_s + HH;              // [512]

    const int b   = blockIdx.x;
    const int tid = threadIdx.x;

    // Register-resident W_hh[g][0..63]
    float4 wr[KREG / 4];
    {
        const float4* Wg = reinterpret_cast<const float4*>(W_hh + (size_t)tid * HH);
#pragma unroll
        for (int i = 0; i < KREG / 4; i++) wr[i] = Wg[i];
    }
    // SMEM-resident W_hh[g][64..127], stored transposed Wt_s[ks][g]
    for (int idx = tid; idx < KSMEM * GG; idx += 512) {
        int g2 = idx & (GG - 1);
        int ks = idx >> 9;
        Wt_s[idx] = W_hh[(size_t)g2 * HH + KREG + ks];
    }
    float c = 0.f;
    if (tid < HH) h_s[tid] = 0.f;
    __syncthreads();

    const float* xp = g_xproj + (size_t)b * TT * GG;
    const float4* h4s = reinterpret_cast<const float4*>(h_s);

    for (int t = 0; t < TT; t++) {
        float acc = xp[t * GG + tid];
        float acc2 = 0.f;
#pragma unroll
        for (int k4 = 0; k4 < KREG / 4; k4++) {
            float4 h4 = h4s[k4];
            acc  += wr[k4].x * h4.x;
            acc2 += wr[k4].y * h4.y;
            acc  += wr[k4].z * h4.z;
            acc2 += wr[k4].w * h4.w;
        }
#pragma unroll
        for (int k4 = KREG / 4; k4 < HH / 4; k4++) {
            float4 h4 = h4s[k4];
            int ks = (k4 - KREG / 4) * 4;
            acc  += Wt_s[(ks + 0) * GG + tid] * h4.x;
            acc2 += Wt_s[(ks + 1) * GG + tid] * h4.y;
            acc  += Wt_s[(ks + 2) * GG + tid] * h4.z;
            acc2 += Wt_s[(ks + 3) * GG + tid] * h4.w;
        }
        gates_s[tid] = acc + acc2;
        __syncthreads();
        if (tid < HH) {
            float ig = sigmoidf_(gates_s[tid]);
            float fg = sigmoidf_(gates_s[HH + tid]);
            float gg = tanhf(gates_s[2 * HH + tid]);
            float og = sigmoidf_(gates_s[3 * HH + tid]);
            c = fg * c + ig * gg;
            float h = og * tanhf(c);
            h_s[tid] = h;
            g_hs[((size_t)b * TT + t) * HH + tid] = h;
        }
        __syncthreads();
    }

    if (tid < HH && out_size >= (long long)FULL_OUT) {
        out[HF_OFF + (size_t)b * HH + tid] = h_s[tid];
        out[CF_OFF + (size_t)b * HH + tid] = c;
    }
}

// ---------------------------------------------------------------------------
// Kernel 3: logits GEMM  out[bt][v] = hs[bt][:] . W_fc[v][:] + b_fc[v]
// 128x128 tiles, K=128 (full), 256 threads, 8x8 micro-tiles via fma.rn.f32x2
// ---------------------------------------------------------------------------
#define SMEM3_BYTES (2 * 128 * 128 * 4)

__device__ __forceinline__ unsigned long long fma2_(unsigned long long a,
                                                    unsigned long long b,
                                                    unsigned long long c) {
#if __CUDA_ARCH__ >= 1000
    unsigned long long d;
    asm("fma.rn.f32x2 %0, %1, %2, %3;" : "=l"(d) : "l"(a), "l"(b), "l"(c));
    return d;
#else
    float2 af = *reinterpret_cast<float2*>(&a);
    float2 bf = *reinterpret_cast<float2*>(&b);
    float2 cf = *reinterpret_cast<float2*>(&c);
    cf.x = fmaf(af.x, bf.x, cf.x);
    cf.y = fmaf(af.y, bf.y, cf.y);
    return *reinterpret_cast<unsigned long long*>(&cf);
#endif
}
__device__ __forceinline__ unsigned long long pack2_(float x, float y) {
    unsigned long long d;
    asm("mov.b64 %0, {%1, %2};" : "=l"(d) : "f"(x), "f"(y));
    return d;
}
__device__ __forceinline__ void unpack2_(unsigned long long v, float& x, float& y) {
    asm("mov.b64 {%0, %1}, %2;" : "=f"(x), "=f"(y) : "l"(v));
}

__global__ __launch_bounds__(256, 1) void k_logits(
    const float* __restrict__ W_fc, const float* __restrict__ b_fc,
    float* __restrict__ out)
{
    extern __shared__ float smem3[];
    float* As = smem3;             // [k][r] 128x128
    float* Bs = smem3 + 128 * 128; // [k][c] 128x128

    const int v0  = blockIdx.x * 128;
    const int bt0 = blockIdx.y * 128;
    const int tid = threadIdx.x;

    // Load + transpose A (hs) and B (W_fc) into k-major smem.
    const float4* hs4 = reinterpret_cast<const float4*>(g_hs);
    const float4* wf4 = reinterpret_cast<const float4*>(W_fc);
    for (int i = tid; i < 128 * 32; i += 256) {
        int r  = i & 127;
        int k4 = i >> 7;
        float4 a = hs4[(size_t)(bt0 + r) * 32 + k4];
        As[(4 * k4 + 0) * 128 + r] = a.x;
        As[(4 * k4 + 1) * 128 + r] = a.y;
        As[(4 * k4 + 2) * 128 + r] = a.z;
        As[(4 * k4 + 3) * 128 + r] = a.w;
    }
    for (int i = tid; i < 128 * 32; i += 256) {
        int cc = i & 127;
        int k4 = i >> 7;
        float4 bv = make_float4(0.f, 0.f, 0.f, 0.f);
        if (v0 + cc < VV) bv = wf4[(size_t)(v0 + cc) * 32 + k4];
        Bs[(4 * k4 + 0) * 128 + cc] = bv.x;
        Bs[(4 * k4 + 1) * 128 + cc] = bv.y;
        Bs[(4 * k4 + 2) * 128 + cc] = bv.z;
        Bs[(4 * k4 + 3) * 128 + cc] = bv.w;
    }
    __syncthreads();

    const int tm = (tid >> 4) << 3;   // 0..120 step 8 (16 groups of m)
    const int tn = (tid & 15) << 3;   // 0..120 step 8

    unsigned long long acc2[8][4];
#pragma unroll
    for (int i = 0; i < 8; i++)
#pragma unroll
        for (int j = 0; j < 4; j++) acc2[i][j] = 0ull;

#pragma unroll 4
    for (int k = 0; k < 128; k++) {
        float4 a0 = *reinterpret_cast<const float4*>(As + k * 128 + tm);
        float4 a1 = *reinterpret_cast<const float4*>(As + k * 128 + tm + 4);
        const unsigned long long* brow =
            reinterpret_cast<const unsigned long long*>(Bs + k * 128 + tn);
        unsigned long long b2[4];
        b2[0] = brow[0]; b2[1] = brow[1]; b2[2] = brow[2]; b2[3] = brow[3];

        float av[8] = {a0.x, a0.y, a0.z, a0.w, a1.x, a1.y, a1.z, a1.w};
#pragma unroll
        for (int i = 0; i < 8; i++) {
            unsigned long long ai = pack2_(av[i], av[i]);
#pragma unroll
            for (int j = 0; j < 4; j++)
                acc2[i][j] = fma2_(ai, b2[j], acc2[i][j]);
        }
    }

    // Epilogue: bias + store (guarded for v >= 10000)
    float bb[8];
#pragma unroll
    for (int j = 0; j < 8; j++)
        bb[j] = (v0 + tn + j < VV) ? b_fc[v0 + tn + j] : 0.f;

#pragma unroll
    for (int i = 0; i < 8; i++) {
        size_t row = (size_t)(bt0 + tm + i) * VV + v0 + tn;
#pragma unroll
        for (int j = 0; j < 4; j++) {
            float lo, hi;
            unpack2_(acc2[i][j], lo, hi);
            int col0 = tn + 2 * j;                       // global-in-tile column
            if (v0 + col0 < VV)     out[row + 2 * j]     = lo + bb[2 * j];
            if (v0 + col0 + 1 < VV) out[row + 2 * j + 1] = hi + bb[2 * j + 1];
        }
    }
}

// ---------------------------------------------------------------------------
extern "C" void kernel_launch(void* const* d_in, const int* in_sizes, int n_in,
                              void* d_out, int out_size)
{
    const int*   x    = (const int*)  d_in[0];
    const float* emb  = (const float*)d_in[1];
    const float* W_ih = (const float*)d_in[2];
    const float* W_hh = (const float*)d_in[3];
    const float* b_ih = (const float*)d_in[4];
    const float* b_hh = (const float*)d_in[5];
    const float* W_fc = (const float*)d_in[6];
    const float* b_fc = (const float*)d_in[7];
    float* out = (float*)d_out;

    cudaFuncSetAttribute(k_lstm,   cudaFuncAttributeMaxDynamicSharedMemorySize, SMEM2_BYTES);
    cudaFuncSetAttribute(k_logits, cudaFuncAttributeMaxDynamicSharedMemorySize, SMEM3_BYTES);

    // 1) embedding + input projection
    k_embed_proj<<<BT / 16, 512>>>(x, emb, W_ih, b_ih, b_hh);

    // 2) recurrence (writes hs scratch + h_n/c_n tail of out)
    k_lstm<<<BB, 512, SMEM2_BYTES>>>(W_hh, out, (long long)out_size);

    // 3) logits GEMM
    dim3 g3((VV + 127) / 128, BT / 128);
    k_logits<<<g3, 256, SMEM3_BYTES>>>(W_fc, b_fc, out);
}

// round 5
// speedup vs baseline: 1.6911x; 1.6911x over previous
#include <cuda_runtime.h>
#include <cuda_bf16.h>
#include <cstdint>

// Problem constants (fixed shapes)
#define BB   64
#define TT   256
#define VV   10000
#define VPAD 10240
#define EE   100
#define HH   128
#define GG   512          // 4H
#define BT   (BB*TT)      // 16384
#define KSPLIT 384        // [hi|hi|lo] x [hi|lo|hi] concatenated K

#define LOGITS_ELEMS ((size_t)BT * VV)          // 163,840,000
#define HF_OFF  LOGITS_ELEMS
#define CF_OFF  (LOGITS_ELEMS + (size_t)BB*HH)
#define FULL_OUT (LOGITS_ELEMS + 2ull*BB*HH)

// Scratch (device globals; allocation-free per harness rules)
__device__ float         g_xproj[(size_t)BT * GG];        // 33.5 MB
__device__ __nv_bfloat16 g_hs_split[(size_t)BT * KSPLIT]; // 12.6 MB  [bt][hi|hi|lo]
__device__ __nv_bfloat16 g_wfc_split[(size_t)VPAD * KSPLIT]; // 7.9 MB [v][hi|lo|hi]

// ---------------------------------------------------------------------------
// Helpers (arch-generic: ldmatrix / mma.sync / cp.async — valid on compute_103)
// ---------------------------------------------------------------------------
__device__ __forceinline__ uint32_t smem_u32(const void* p) {
    uint32_t a;
    asm("{ .reg .u64 t; cvta.to.shared.u64 t, %1; cvt.u32.u64 %0, t; }" : "=r"(a) : "l"(p));
    return a;
}
__device__ __forceinline__ void cp16(uint32_t dst, const void* src) {
    asm volatile("cp.async.cg.shared.global [%0], [%1], 16;" :: "r"(dst), "l"(src));
}
#define CP_COMMIT() asm volatile("cp.async.commit_group;" ::: "memory")
#define CP_WAIT(n)  asm volatile("cp.async.wait_group %0;" :: "n"(n) : "memory")

__device__ __forceinline__ void ldm4(uint32_t* r, uint32_t addr) {
    asm volatile("ldmatrix.sync.aligned.m8n8.x4.shared.b16 {%0,%1,%2,%3}, [%4];"
                 : "=r"(r[0]), "=r"(r[1]), "=r"(r[2]), "=r"(r[3]) : "r"(addr));
}
__device__ __forceinline__ void mma16816(float* c, const uint32_t* a,
                                         uint32_t b0, uint32_t b1) {
    asm volatile(
        "mma.sync.aligned.m16n8k16.row.col.f32.bf16.bf16.f32 "
        "{%0,%1,%2,%3}, {%4,%5,%6,%7}, {%8,%9}, {%0,%1,%2,%3};"
        : "+f"(c[0]), "+f"(c[1]), "+f"(c[2]), "+f"(c[3])
        : "r"(a[0]), "r"(a[1]), "r"(a[2]), "r"(a[3]), "r"(b0), "r"(b1));
}

// ---------------------------------------------------------------------------
// Kernel 1: embedding gather + input projection (unchanged)
// ---------------------------------------------------------------------------
__global__ __launch_bounds__(512) void k_embed_proj(
    const int* __restrict__ x, const float* __restrict__ emb,
    const float* __restrict__ W_ih, const float* __restrict__ b_ih,
    const float* __restrict__ b_hh)
{
    __shared__ float xe_s[16 * EE];
    __shared__ int   toks[16];
    const int bt0 = blockIdx.x * 16;
    const int tid = threadIdx.x;

    if (tid < 16) toks[tid] = x[bt0 + tid];
    __syncthreads();
    for (int i = tid; i < 16 * EE; i += 512) {
        int r = i / EE, e = i - r * EE;
        xe_s[i] = emb[(size_t)toks[r] * EE + e];
    }
    __syncthreads();

    const int g = tid;
    float acc[16];
#pragma unroll
    for (int r = 0; r < 16; r++) acc[r] = 0.f;

    const float4* W4 = reinterpret_cast<const float4*>(W_ih + (size_t)g * EE);
#pragma unroll 5
    for (int e4 = 0; e4 < EE / 4; e4++) {
        float4 w = W4[e4];
#pragma unroll
        for (int r = 0; r < 16; r++) {
            float4 v = reinterpret_cast<const float4*>(xe_s + r * EE)[e4];
            acc[r] += w.x * v.x;
            acc[r] += w.y * v.y;
            acc[r] += w.z * v.z;
            acc[r] += w.w * v.w;
        }
    }
    const float bias = b_ih[g] + b_hh[g];
#pragma unroll
    for (int r = 0; r < 16; r++)
        g_xproj[(size_t)(bt0 + r) * GG + g] = acc[r] + bias;
}

// ---------------------------------------------------------------------------
// Kernel 2: LSTM recurrence (emits hs as [hi|hi|lo] bf16 triple)
// ---------------------------------------------------------------------------
#define KREG  64
#define KSMEM 64
#define SMEM2_BYTES ((KSMEM*GG + HH + GG) * 4)

__device__ __forceinline__ float sigmoidf_(float v) {
    return 1.f / (1.f + expf(-v));
}

__global__ __launch_bounds__(512, 1) void k_lstm(
    const float* __restrict__ W_hh, float* __restrict__ out, long long out_size)
{
    extern __shared__ float smem2[];
    float* Wt_s    = smem2;                 // [KSMEM][512]
    float* h_s     = smem2 + KSMEM * GG;    // [128]
    float* gates_s = h_s + HH;              // [512]

    const int b   = blockIdx.x;
    const int tid = threadIdx.x;

    float4 wr[KREG / 4];
    {
        const float4* Wg = reinterpret_cast<const float4*>(W_hh + (size_t)tid * HH);
#pragma unroll
        for (int i = 0; i < KREG / 4; i++) wr[i] = Wg[i];
    }
    for (int idx = tid; idx < KSMEM * GG; idx += 512) {
        int g2 = idx & (GG - 1);
        int ks = idx >> 9;
        Wt_s[idx] = W_hh[(size_t)g2 * HH + KREG + ks];
    }
    float c = 0.f;
    if (tid < HH) h_s[tid] = 0.f;
    __syncthreads();

    const float* xp = g_xproj + (size_t)b * TT * GG;
    const float4* h4s = reinterpret_cast<const float4*>(h_s);

    for (int t = 0; t < TT; t++) {
        float acc = xp[t * GG + tid];
        float acc2 = 0.f;
#pragma unroll
        for (int k4 = 0; k4 < KREG / 4; k4++) {
            float4 h4 = h4s[k4];
            acc  += wr[k4].x * h4.x;
            acc2 += wr[k4].y * h4.y;
            acc  += wr[k4].z * h4.z;
            acc2 += wr[k4].w * h4.w;
        }
#pragma unroll
        for (int k4 = KREG / 4; k4 < HH / 4; k4++) {
            float4 h4 = h4s[k4];
            int ks = (k4 - KREG / 4) * 4;
            acc  += Wt_s[(ks + 0) * GG + tid] * h4.x;
            acc2 += Wt_s[(ks + 1) * GG + tid] * h4.y;
            acc  += Wt_s[(ks + 2) * GG + tid] * h4.z;
            acc2 += Wt_s[(ks + 3) * GG + tid] * h4.w;
        }
        gates_s[tid] = acc + acc2;
        __syncthreads();
        if (tid < HH) {
            float ig = sigmoidf_(gates_s[tid]);
            float fg = sigmoidf_(gates_s[HH + tid]);
            float gg = tanhf(gates_s[2 * HH + tid]);
            float og = sigmoidf_(gates_s[3 * HH + tid]);
            c = fg * c + ig * gg;
            float h = og * tanhf(c);
            h_s[tid] = h;
            __nv_bfloat16 hh = __float2bfloat16(h);
            float          hl = h - __bfloat162float(hh);
            size_t base = ((size_t)b * TT + t) * KSPLIT;
            g_hs_split[base + tid]       = hh;
            g_hs_split[base + 128 + tid] = hh;
            g_hs_split[base + 256 + tid] = __float2bfloat16(hl);
        }
        __syncthreads();
    }

    if (tid < HH && out_size >= (long long)FULL_OUT) {
        out[HF_OFF + (size_t)b * HH + tid] = h_s[tid];
        out[CF_OFF + (size_t)b * HH + tid] = c;
    }
}

// ---------------------------------------------------------------------------
// Kernel 2b: split W_fc into [hi|lo|hi] bf16 triple, zero-padded to VPAD rows
// ---------------------------------------------------------------------------
__global__ __launch_bounds__(256) void k_split_wfc(const float* __restrict__ W_fc)
{
    size_t i = (size_t)blockIdx.x * 256 + threadIdx.x;   // over VPAD*HH
    int v = (int)(i >> 7);
    int k = (int)(i & 127);
    float w = (v < VV) ? W_fc[i] : 0.f;
    __nv_bfloat16 hi = __float2bfloat16(w);
    float lo = w - __bfloat162float(hi);
    size_t base = (size_t)v * KSPLIT;
    g_wfc_split[base + k]       = hi;
    g_wfc_split[base + 128 + k] = __float2bfloat16(lo);
    g_wfc_split[base + 256 + k] = hi;
}

// ---------------------------------------------------------------------------
// Kernel 3: logits GEMM via mma.sync (bf16-split K=384, fp32 accum)
// 128x128 block tile, BK=64 chunks (6), cp.async double buffer.
// 8 warps as 2(m) x 4(n); warp tile 64x32 = 4x4 m16n8k16 tiles.
// SMEM rows are 128B (64 bf16), XOR-swizzled at 16B granularity.
// ---------------------------------------------------------------------------
#define NK 6
#define SA0 0
#define SB0 16384
#define SA1 32768
#define SB1 49152
#define SMEM3_BYTES 65536

__device__ __forceinline__ void load_chunk(
    uint32_t smem_base, int abuf, int bbuf,
    const __nv_bfloat16* __restrict__ asrc,   // + bt0*KSPLIT
    const __nv_bfloat16* __restrict__ bsrc,   // + v0*KSPLIT
    int kc, int tid)
{
    const int k0 = kc * 64;
#pragma unroll
    for (int it = 0; it < 4; it++) {
        int i = tid + it * 256;          // 0..1023
        int row = i >> 3;
        int j   = i & 7;
        uint32_t dst = smem_base + abuf + row * 128 + ((j ^ (row & 7)) << 4);
        cp16(dst, asrc + (size_t)row * KSPLIT + k0 + j * 8);
    }
#pragma unroll
    for (int it = 0; it < 4; it++) {
        int i = tid + it * 256;
        int row = i >> 3;
        int j   = i & 7;
        uint32_t dst = smem_base + bbuf + row * 128 + ((j ^ (row & 7)) << 4);
        cp16(dst, bsrc + (size_t)row * KSPLIT + k0 + j * 8);
    }
}

__global__ __launch_bounds__(256, 2) void k_logits_mma(
    const float* __restrict__ b_fc, float* __restrict__ out)
{
    extern __shared__ char smem3[];
    const uint32_t smem_base = smem_u32(smem3);
    const int tid = threadIdx.x;
    const int wid = tid >> 5;
    const int l   = tid & 31;
    const int v0  = blockIdx.x * 128;
    const int bt0 = blockIdx.y * 128;

    const __nv_bfloat16* asrc = g_hs_split + (size_t)bt0 * KSPLIT;
    const __nv_bfloat16* bsrc = g_wfc_split + (size_t)v0 * KSPLIT;

    const int wm = (wid >> 2) * 64;   // warp m offset (0/64)
    const int wn = (wid & 3) * 32;    // warp n offset (0..96)

    float c[4][4][4];
#pragma unroll
    for (int mi = 0; mi < 4; mi++)
#pragma unroll
        for (int nj = 0; nj < 4; nj++)
#pragma unroll
            for (int q = 0; q < 4; q++) c[mi][nj][q] = 0.f;

    // per-lane ldmatrix row/sel invariants
    const int lrow = l & 15;
    const int lsel = l >> 4;          // 0/1 -> +8 k elements -> +1 chunk

    // prologue: chunk 0 -> buf 0
    load_chunk(smem_base, SA0, SB0, asrc, bsrc, 0, tid);
    CP_COMMIT();

#pragma unroll
    for (int kc = 0; kc < NK; kc++) {
        const int abuf = (kc & 1) ? SA1 : SA0;
        const int bbuf = (kc & 1) ? SB1 : SB0;
        if (kc + 1 < NK) {
            load_chunk(smem_base, (kc & 1) ? SA0 : SA1, (kc & 1) ? SB0 : SB1,
                       asrc, bsrc, kc + 1, tid);
            CP_COMMIT();
            CP_WAIT(1);
        } else {
            CP_WAIT(0);
        }
        __syncthreads();

#pragma unroll
        for (int k16 = 0; k16 < 4; k16++) {
            const int j = 2 * k16 + lsel;
            uint32_t a[4][4];
#pragma unroll
            for (int mi = 0; mi < 4; mi++) {
                int r = wm + mi * 16 + lrow;
                ldm4(a[mi], smem_base + abuf + r * 128 + ((j ^ (r & 7)) << 4));
            }
            uint32_t bfr[2][4];
#pragma unroll
            for (int njp = 0; njp < 2; njp++) {
                int r = wn + njp * 16 + lrow;
                ldm4(bfr[njp], smem_base + bbuf + r * 128 + ((j ^ (r & 7)) << 4));
            }
#pragma unroll
            for (int mi = 0; mi < 4; mi++) {
#pragma unroll
                for (int njp = 0; njp < 2; njp++) {
                    mma16816(c[mi][njp * 2 + 0], a[mi], bfr[njp][0], bfr[njp][2]);
                    mma16816(c[mi][njp * 2 + 1], a[mi], bfr[njp][1], bfr[njp][3]);
                }
            }
        }
        __syncthreads();
    }

    // Epilogue: bias + guarded float2 stores
    const int g  = l >> 2;
    const int q  = l & 3;
    const int mB = bt0 + wm;
    const int nB = v0 + wn;

#pragma unroll
    for (int nj = 0; nj < 4; nj++) {
        const int v = nB + nj * 8 + 2 * q;
        if (v >= VV) continue;
        const float2 bias = *reinterpret_cast<const float2*>(b_fc + v);
#pragma unroll
        for (int mi = 0; mi < 4; mi++) {
            const float* cc = c[mi][nj];
            const int r0 = mB + mi * 16 + g;
            float2 o0 = make_float2(cc[0] + bias.x, cc[1] + bias.y);
            float2 o1 = make_float2(cc[2] + bias.x, cc[3] + bias.y);
            *reinterpret_cast<float2*>(out + (size_t)r0 * VV + v)       = o0;
            *reinterpret_cast<float2*>(out + (size_t)(r0 + 8) * VV + v) = o1;
        }
    }
}

// ---------------------------------------------------------------------------
extern "C" void kernel_launch(void* const* d_in, const int* in_sizes, int n_in,
                              void* d_out, int out_size)
{
    const int*   x    = (const int*)  d_in[0];
    const float* emb  = (const float*)d_in[1];
    const float* W_ih = (const float*)d_in[2];
    const float* W_hh = (const float*)d_in[3];
    const float* b_ih = (const float*)d_in[4];
    const float* b_hh = (const float*)d_in[5];
    const float* W_fc = (const float*)d_in[6];
    const float* b_fc = (const float*)d_in[7];
    float* out = (float*)d_out;

    cudaFuncSetAttribute(k_lstm,       cudaFuncAttributeMaxDynamicSharedMemorySize, SMEM2_BYTES);
    cudaFuncSetAttribute(k_logits_mma, cudaFuncAttributeMaxDynamicSharedMemorySize, SMEM3_BYTES);

    // 1) embedding + input projection
    k_embed_proj<<<BT / 16, 512>>>(x, emb, W_ih, b_ih, b_hh);

    // 1b) W_fc bf16 split (independent of 1/2)
    k_split_wfc<<<(VPAD * HH) / 256, 256>>>(W_fc);

    // 2) recurrence (writes hs split + h_n/c_n tail of out)
    k_lstm<<<BB, 512, SMEM2_BYTES>>>(W_hh, out, (long long)out_size);

    // 3) logits GEMM on HMMA tensor cores
    dim3 g3(VPAD / 128, BT / 128);
    k_logits_mma<<<g3, 256, SMEM3_BYTES>>>(b_fc, out);
}

// round 6
// speedup vs baseline: 2.7820x; 1.6451x over previous
#include <cuda_runtime.h>
#include <cuda_bf16.h>
#include <cstdint>

// Problem constants (fixed shapes)
#define BB   64
#define TT   256
#define VV   10000
#define VPAD 10240
#define EE   100
#define HH   128
#define GG   512          // 4H
#define BT   (BB*TT)      // 16384
#define KSPLIT 384        // [hi|hi|lo] x [hi|lo|hi] concatenated K

#define LOGITS_ELEMS ((size_t)BT * VV)          // 163,840,000
#define HF_OFF  LOGITS_ELEMS
#define CF_OFF  (LOGITS_ELEMS + (size_t)BB*HH)
#define FULL_OUT (LOGITS_ELEMS + 2ull*BB*HH)

// Scratch (device globals; allocation-free per harness rules)
__device__ float         g_xproj[(size_t)BT * GG];        // 33.5 MB
__device__ __nv_bfloat16 g_hs_split[(size_t)BT * KSPLIT]; // 12.6 MB  [bt][hi|hi|lo]
__device__ __nv_bfloat16 g_wfc_split[(size_t)VPAD * KSPLIT]; // 7.9 MB [v][hi|lo|hi]

// ---------------------------------------------------------------------------
// Helpers (arch-generic: ldmatrix / mma.sync / cp.async — valid on compute_103)
// ---------------------------------------------------------------------------
__device__ __forceinline__ uint32_t smem_u32(const void* p) {
    uint32_t a;
    asm("{ .reg .u64 t; cvta.to.shared.u64 t, %1; cvt.u32.u64 %0, t; }" : "=r"(a) : "l"(p));
    return a;
}
__device__ __forceinline__ void cp16(uint32_t dst, const void* src) {
    asm volatile("cp.async.cg.shared.global [%0], [%1], 16;" :: "r"(dst), "l"(src));
}
#define CP_COMMIT() asm volatile("cp.async.commit_group;" ::: "memory")
#define CP_WAIT(n)  asm volatile("cp.async.wait_group %0;" :: "n"(n) : "memory")

__device__ __forceinline__ void ldm4(uint32_t* r, uint32_t addr) {
    asm volatile("ldmatrix.sync.aligned.m8n8.x4.shared.b16 {%0,%1,%2,%3}, [%4];"
                 : "=r"(r[0]), "=r"(r[1]), "=r"(r[2]), "=r"(r[3]) : "r"(addr));
}
__device__ __forceinline__ void mma16816(float* c, const uint32_t* a,
                                         uint32_t b0, uint32_t b1) {
    asm volatile(
        "mma.sync.aligned.m16n8k16.row.col.f32.bf16.bf16.f32 "
        "{%0,%1,%2,%3}, {%4,%5,%6,%7}, {%8,%9}, {%0,%1,%2,%3};"
        : "+f"(c[0]), "+f"(c[1]), "+f"(c[2]), "+f"(c[3])
        : "r"(a[0]), "r"(a[1]), "r"(a[2]), "r"(a[3]), "r"(b0), "r"(b1));
}

// Fast, saturation-safe activations (MUFU EX2 based)
__device__ __forceinline__ float sigm_fast(float x) {
    return 1.f / (1.f + __expf(-x));
}
__device__ __forceinline__ float tanh_fast(float x) {
    // 2*sigmoid(2x)-1: large +x -> expf(-2x)=0 -> 1; large -x -> expf=inf -> -1
    return 2.f / (1.f + __expf(-2.f * x)) - 1.f;
}

// ---------------------------------------------------------------------------
// Kernel 1: embedding gather + input projection
// ---------------------------------------------------------------------------
__global__ __launch_bounds__(512) void k_embed_proj(
    const int* __restrict__ x, const float* __restrict__ emb,
    const float* __restrict__ W_ih, const float* __restrict__ b_ih,
    const float* __restrict__ b_hh)
{
    __shared__ float xe_s[16 * EE];
    __shared__ int   toks[16];
    const int bt0 = blockIdx.x * 16;
    const int tid = threadIdx.x;

    if (tid < 16) toks[tid] = x[bt0 + tid];
    __syncthreads();
    for (int i = tid; i < 16 * EE; i += 512) {
        int r = i / EE, e = i - r * EE;
        xe_s[i] = emb[(size_t)toks[r] * EE + e];
    }
    __syncthreads();

    const int g = tid;
    float acc[16];
#pragma unroll
    for (int r = 0; r < 16; r++) acc[r] = 0.f;

    const float4* W4 = reinterpret_cast<const float4*>(W_ih + (size_t)g * EE);
#pragma unroll 5
    for (int e4 = 0; e4 < EE / 4; e4++) {
        float4 w = W4[e4];
#pragma unroll
        for (int r = 0; r < 16; r++) {
            float4 v = reinterpret_cast<const float4*>(xe_s + r * EE)[e4];
            acc[r] += w.x * v.x;
            acc[r] += w.y * v.y;
            acc[r] += w.z * v.z;
            acc[r] += w.w * v.w;
        }
    }
    const float bias = b_ih[g] + b_hh[g];
#pragma unroll
    for (int r = 0; r < 16; r++)
        g_xproj[(size_t)(bt0 + r) * GG + g] = acc[r] + bias;
}

// ---------------------------------------------------------------------------
// Kernel 2: LSTM recurrence. Activations applied by the owning gate thread
// (512-wide), combine (tid<128) does only c/h update + one tanh.
// ---------------------------------------------------------------------------
#define KREG  64
#define KSMEM 64
#define SMEM2_BYTES ((KSMEM*GG + HH + GG) * 4)

__global__ __launch_bounds__(512, 1) void k_lstm(
    const float* __restrict__ W_hh, float* __restrict__ out, long long out_size)
{
    extern __shared__ float smem2[];
    float* Wt_s    = smem2;                 // [KSMEM][512]
    float* h_s     = smem2 + KSMEM * GG;    // [128]
    float* gates_s = h_s + HH;              // [512] (activated)

    const int b   = blockIdx.x;
    const int tid = threadIdx.x;
    const int q   = tid >> 7;               // gate quarter: 0=i 1=f 2=g 3=o

    float4 wr[KREG / 4];
    {
        const float4* Wg = reinterpret_cast<const float4*>(W_hh + (size_t)tid * HH);
#pragma unroll
        for (int i = 0; i < KREG / 4; i++) wr[i] = Wg[i];
    }
    for (int idx = tid; idx < KSMEM * GG; idx += 512) {
        int g2 = idx & (GG - 1);
        int ks = idx >> 9;
        Wt_s[idx] = W_hh[(size_t)g2 * HH + KREG + ks];
    }
    float c = 0.f;
    if (tid < HH) h_s[tid] = 0.f;
    __syncthreads();

    const float* xp = g_xproj + (size_t)b * TT * GG;
    const float4* h4s = reinterpret_cast<const float4*>(h_s);

    float xnext = xp[tid];                   // prefetch t=0

    for (int t = 0; t < TT; t++) {
        float acc = xnext;
        float acc2 = 0.f;
        if (t + 1 < TT) xnext = __ldg(xp + (t + 1) * GG + tid);  // hide latency

#pragma unroll
        for (int k4 = 0; k4 < KREG / 4; k4++) {
            float4 h4 = h4s[k4];
            acc  += wr[k4].x * h4.x;
            acc2 += wr[k4].y * h4.y;
            acc  += wr[k4].z * h4.z;
            acc2 += wr[k4].w * h4.w;
        }
#pragma unroll
        for (int k4 = KREG / 4; k4 < HH / 4; k4++) {
            float4 h4 = h4s[k4];
            int ks = (k4 - KREG / 4) * 4;
            acc  += Wt_s[(ks + 0) * GG + tid] * h4.x;
            acc2 += Wt_s[(ks + 1) * GG + tid] * h4.y;
            acc  += Wt_s[(ks + 2) * GG + tid] * h4.z;
            acc2 += Wt_s[(ks + 3) * GG + tid] * h4.w;
        }
        const float gv = acc + acc2;
        gates_s[tid] = (q == 2) ? tanh_fast(gv) : sigm_fast(gv);
        __syncthreads();

        if (tid < HH) {
            float ig = gates_s[tid];
            float fg = gates_s[HH + tid];
            float gg = gates_s[2 * HH + tid];
            float og = gates_s[3 * HH + tid];
            c = fg * c + ig * gg;
            float h = og * tanh_fast(c);
            h_s[tid] = h;
            __nv_bfloat16 hh = __float2bfloat16(h);
            float          hl = h - __bfloat162float(hh);
            size_t base = ((size_t)b * TT + t) * KSPLIT;
            g_hs_split[base + tid]       = hh;
            g_hs_split[base + 128 + tid] = hh;
            g_hs_split[base + 256 + tid] = __float2bfloat16(hl);
        }
        __syncthreads();
    }

    if (tid < HH && out_size >= (long long)FULL_OUT) {
        out[HF_OFF + (size_t)b * HH + tid] = h_s[tid];
        out[CF_OFF + (size_t)b * HH + tid] = c;
    }
}

// ---------------------------------------------------------------------------
// Kernel 2b: split W_fc into [hi|lo|hi] bf16 triple, zero-padded to VPAD rows
// ---------------------------------------------------------------------------
__global__ __launch_bounds__(256) void k_split_wfc(const float* __restrict__ W_fc)
{
    size_t i = (size_t)blockIdx.x * 256 + threadIdx.x;   // over VPAD*HH
    int v = (int)(i >> 7);
    int k = (int)(i & 127);
    float w = (v < VV) ? W_fc[i] : 0.f;
    __nv_bfloat16 hi = __float2bfloat16(w);
    float lo = w - __bfloat162float(hi);
    size_t base = (size_t)v * KSPLIT;
    g_wfc_split[base + k]       = hi;
    g_wfc_split[base + 128 + k] = __float2bfloat16(lo);
    g_wfc_split[base + 256 + k] = hi;
}

// ---------------------------------------------------------------------------
// Kernel 3: logits GEMM via mma.sync (bf16-split K=384, fp32 accum)
// 128x128 block tile, BK=64 chunks (6), 3-stage cp.async ring, 1 barrier/chunk.
// 8 warps as 2(m) x 4(n); warp tile 64x32 = 4x4 m16n8k16 tiles.
// ---------------------------------------------------------------------------
#define NK 6
#define STAGE_BYTES 32768          // A 16KB + B 16KB
#define SMEM3_BYTES (3 * STAGE_BYTES)

__device__ __forceinline__ void load_chunk(
    uint32_t smem_base, int stage,
    const __nv_bfloat16* __restrict__ asrc,   // + bt0*KSPLIT
    const __nv_bfloat16* __restrict__ bsrc,   // + v0*KSPLIT
    int kc, int tid)
{
    const int abuf = stage * STAGE_BYTES;
    const int bbuf = abuf + 16384;
    const int k0 = kc * 64;
#pragma unroll
    for (int it = 0; it < 4; it++) {
        int i = tid + it * 256;          // 0..1023
        int row = i >> 3;
        int j   = i & 7;
        uint32_t dst = smem_base + abuf + row * 128 + ((j ^ (row & 7)) << 4);
        cp16(dst, asrc + (size_t)row * KSPLIT + k0 + j * 8);
    }
#pragma unroll
    for (int it = 0; it < 4; it++) {
        int i = tid + it * 256;
        int row = i >> 3;
        int j   = i & 7;
        uint32_t dst = smem_base + bbuf + row * 128 + ((j ^ (row & 7)) << 4);
        cp16(dst, bsrc + (size_t)row * KSPLIT + k0 + j * 8);
    }
}

__global__ __launch_bounds__(256, 2) void k_logits_mma(
    const float* __restrict__ b_fc, float* __restrict__ out)
{
    extern __shared__ char smem3[];
    const uint32_t smem_base = smem_u32(smem3);
    const int tid = threadIdx.x;
    const int wid = tid >> 5;
    const int l   = tid & 31;
    const int v0  = blockIdx.x * 128;
    const int bt0 = blockIdx.y * 128;

    const __nv_bfloat16* asrc = g_hs_split + (size_t)bt0 * KSPLIT;
    const __nv_bfloat16* bsrc = g_wfc_split + (size_t)v0 * KSPLIT;

    const int wm = (wid >> 2) * 64;   // warp m offset (0/64)
    const int wn = (wid & 3) * 32;    // warp n offset (0..96)

    float c[4][4][4];
#pragma unroll
    for (int mi = 0; mi < 4; mi++)
#pragma unroll
        for (int nj = 0; nj < 4; nj++)
#pragma unroll
            for (int qq = 0; qq < 4; qq++) c[mi][nj][qq] = 0.f;

    const int lrow = l & 15;
    const int lsel = l >> 4;

    // prologue: 2 stages in flight
    load_chunk(smem_base, 0, asrc, bsrc, 0, tid);
    CP_COMMIT();
    load_chunk(smem_base, 1, asrc, bsrc, 1, tid);
    CP_COMMIT();

#pragma unroll
    for (int kc = 0; kc < NK; kc++) {
        if (kc < NK - 1) { CP_WAIT(1); } else { CP_WAIT(0); }
        __syncthreads();                       // chunk kc visible; prev compute done
        if (kc + 2 < NK) {
            load_chunk(smem_base, (kc + 2) % 3, asrc, bsrc, kc + 2, tid);
            CP_COMMIT();
        }

        const int abuf = (kc % 3) * STAGE_BYTES;
        const int bbuf = abuf + 16384;
#pragma unroll
        for (int k16 = 0; k16 < 4; k16++) {
            const int j = 2 * k16 + lsel;
            uint32_t a[4][4];
#pragma unroll
            for (int mi = 0; mi < 4; mi++) {
                int r = wm + mi * 16 + lrow;
                ldm4(a[mi], smem_base + abuf + r * 128 + ((j ^ (r & 7)) << 4));
            }
            uint32_t bfr[2][4];
#pragma unroll
            for (int njp = 0; njp < 2; njp++) {
                int r = wn + njp * 16 + lrow;
                ldm4(bfr[njp], smem_base + bbuf + r * 128 + ((j ^ (r & 7)) << 4));
            }
#pragma unroll
            for (int mi = 0; mi < 4; mi++) {
#pragma unroll
                for (int njp = 0; njp < 2; njp++) {
                    mma16816(c[mi][njp * 2 + 0], a[mi], bfr[njp][0], bfr[njp][2]);
                    mma16816(c[mi][njp * 2 + 1], a[mi], bfr[njp][1], bfr[njp][3]);
                }
            }
        }
    }

    // Epilogue: bias + guarded float2 stores
    const int g  = l >> 2;
    const int qq = l & 3;
    const int mB = bt0 + wm;
    const int nB = v0 + wn;

#pragma unroll
    for (int nj = 0; nj < 4; nj++) {
        const int v = nB + nj * 8 + 2 * qq;
        if (v >= VV) continue;
        const float2 bias = *reinterpret_cast<const float2*>(b_fc + v);
#pragma unroll
        for (int mi = 0; mi < 4; mi++) {
            const float* cc = c[mi][nj];
            const int r0 = mB + mi * 16 + g;
            float2 o0 = make_float2(cc[0] + bias.x, cc[1] + bias.y);
            float2 o1 = make_float2(cc[2] + bias.x, cc[3] + bias.y);
            *reinterpret_cast<float2*>(out + (size_t)r0 * VV + v)       = o0;
            *reinterpret_cast<float2*>(out + (size_t)(r0 + 8) * VV + v) = o1;
        }
    }
}

// ---------------------------------------------------------------------------
extern "C" void kernel_launch(void* const* d_in, const int* in_sizes, int n_in,
                              void* d_out, int out_size)
{
    const int*   x    = (const int*)  d_in[0];
    const float* emb  = (const float*)d_in[1];
    const float* W_ih = (const float*)d_in[2];
    const float* W_hh = (const float*)d_in[3];
    const float* b_ih = (const float*)d_in[4];
    const float* b_hh = (const float*)d_in[5];
    const float* W_fc = (const float*)d_in[6];
    const float* b_fc = (const float*)d_in[7];
    float* out = (float*)d_out;

    cudaFuncSetAttribute(k_lstm,       cudaFuncAttributeMaxDynamicSharedMemorySize, SMEM2_BYTES);
    cudaFuncSetAttribute(k_logits_mma, cudaFuncAttributeMaxDynamicSharedMemorySize, SMEM3_BYTES);

    // 1) embedding + input projection
    k_embed_proj<<<BT / 16, 512>>>(x, emb, W_ih, b_ih, b_hh);

    // 1b) W_fc bf16 split (independent of 1/2)
    k_split_wfc<<<(VPAD * HH) / 256, 256>>>(W_fc);

    // 2) recurrence (writes hs split + h_n/c_n tail of out)
    k_lstm<<<BB, 512, SMEM2_BYTES>>>(W_hh, out, (long long)out_size);

    // 3) logits GEMM on HMMA tensor cores
    dim3 g3(VPAD / 128, BT / 128);
    k_logits_mma<<<g3, 256, SMEM3_BYTES>>>(b_fc, out);
}

// round 7
// speedup vs baseline: 3.0560x; 1.0985x over previous
#include <cuda_runtime.h>
#include <cuda_bf16.h>
#include <cstdint>

// Problem constants (fixed shapes)
#define BB   64
#define TT   256
#define VV   10000
#define VPAD 10240
#define EE   100
#define HH   128
#define GG   512          // 4H
#define BT   (BB*TT)      // 16384
#define KSPLIT 384        // [hi|hi|lo] x [hi|lo|hi] concatenated K

#define LOGITS_ELEMS ((size_t)BT * VV)          // 163,840,000
#define HF_OFF  LOGITS_ELEMS
#define CF_OFF  (LOGITS_ELEMS + (size_t)BB*HH)
#define FULL_OUT (LOGITS_ELEMS + 2ull*BB*HH)

// Scratch (device globals; allocation-free per harness rules)
__device__ float         g_xproj[(size_t)BT * GG];        // 33.5 MB
__device__ __nv_bfloat16 g_hs_split[(size_t)BT * KSPLIT]; // 12.6 MB  [bt][hi|hi|lo]
__device__ __nv_bfloat16 g_wfc_split[(size_t)VPAD * KSPLIT]; // 7.9 MB [v][hi|lo|hi]

// ---------------------------------------------------------------------------
// Helpers (arch-generic: ldmatrix / mma.sync / cp.async — valid on compute_103)
// ---------------------------------------------------------------------------
__device__ __forceinline__ uint32_t smem_u32(const void* p) {
    uint32_t a;
    asm("{ .reg .u64 t; cvta.to.shared.u64 t, %1; cvt.u32.u64 %0, t; }" : "=r"(a) : "l"(p));
    return a;
}
__device__ __forceinline__ void cp16(uint32_t dst, const void* src) {
    asm volatile("cp.async.cg.shared.global [%0], [%1], 16;" :: "r"(dst), "l"(src));
}
#define CP_COMMIT() asm volatile("cp.async.commit_group;" ::: "memory")
#define CP_WAIT(n)  asm volatile("cp.async.wait_group %0;" :: "n"(n) : "memory")

__device__ __forceinline__ void ldm4(uint32_t* r, uint32_t addr) {
    asm volatile("ldmatrix.sync.aligned.m8n8.x4.shared.b16 {%0,%1,%2,%3}, [%4];"
                 : "=r"(r[0]), "=r"(r[1]), "=r"(r[2]), "=r"(r[3]) : "r"(addr));
}
__device__ __forceinline__ void mma16816(float* c, const uint32_t* a,
                                         uint32_t b0, uint32_t b1) {
    asm volatile(
        "mma.sync.aligned.m16n8k16.row.col.f32.bf16.bf16.f32 "
        "{%0,%1,%2,%3}, {%4,%5,%6,%7}, {%8,%9}, {%0,%1,%2,%3};"
        : "+f"(c[0]), "+f"(c[1]), "+f"(c[2]), "+f"(c[3])
        : "r"(a[0]), "r"(a[1]), "r"(a[2]), "r"(a[3]), "r"(b0), "r"(b1));
}

// Fast, saturation-safe activations (MUFU EX2 based)
__device__ __forceinline__ float sigm_fast(float x) {
    return 1.f / (1.f + __expf(-x));
}
__device__ __forceinline__ float tanh_fast(float x) {
    // 2*sigmoid(2x)-1: large +x -> expf(-2x)=0 -> 1; large -x -> expf=inf -> -1
    return 2.f / (1.f + __expf(-2.f * x)) - 1.f;
}

// ---------------------------------------------------------------------------
// Kernel 1: embedding gather + input projection
// ---------------------------------------------------------------------------
__global__ __launch_bounds__(512) void k_embed_proj(
    const int* __restrict__ x, const float* __restrict__ emb,
    const float* __restrict__ W_ih, const float* __restrict__ b_ih,
    const float* __restrict__ b_hh)
{
    __shared__ float xe_s[16 * EE];
    __shared__ int   toks[16];
    const int bt0 = blockIdx.x * 16;
    const int tid = threadIdx.x;

    if (tid < 16) toks[tid] = x[bt0 + tid];
    __syncthreads();
    for (int i = tid; i < 16 * EE; i += 512) {
        int r = i / EE, e = i - r * EE;
        xe_s[i] = emb[(size_t)toks[r] * EE + e];
    }
    __syncthreads();

    const int g = tid;
    float acc[16];
#pragma unroll
    for (int r = 0; r < 16; r++) acc[r] = 0.f;

    const float4* W4 = reinterpret_cast<const float4*>(W_ih + (size_t)g * EE);
#pragma unroll 5
    for (int e4 = 0; e4 < EE / 4; e4++) {
        float4 w = W4[e4];
#pragma unroll
        for (int r = 0; r < 16; r++) {
            float4 v = reinterpret_cast<const float4*>(xe_s + r * EE)[e4];
            acc[r] += w.x * v.x;
            acc[r] += w.y * v.y;
            acc[r] += w.z * v.z;
            acc[r] += w.w * v.w;
        }
    }
    const float bias = b_ih[g] + b_hh[g];
#pragma unroll
    for (int r = 0; r < 16; r++)
        g_xproj[(size_t)(bt0 + r) * GG + g] = acc[r] + bias;
}

// ---------------------------------------------------------------------------
// Kernel 2: LSTM recurrence. 512 threads (one per gate row).
// W_hh k=0..95 in registers (96 regs), k=96..127 in SMEM (transposed [k][g]).
// LDS bytes/step halved vs KREG=64 — smem crossbar was the binding pipe.
// ---------------------------------------------------------------------------
#define KREG  96
#define KSMEM 32
#define SMEM2_BYTES ((KSMEM*GG + HH + GG) * 4)

__global__ __launch_bounds__(512, 1) void k_lstm(
    const float* __restrict__ W_hh, float* __restrict__ out, long long out_size)
{
    extern __shared__ float smem2[];
    float* Wt_s    = smem2;                 // [KSMEM][512]
    float* h_s     = smem2 + KSMEM * GG;    // [128]
    float* gates_s = h_s + HH;              // [512] (activated)

    const int b   = blockIdx.x;
    const int tid = threadIdx.x;
    const int q   = tid >> 7;               // gate quarter: 0=i 1=f 2=g 3=o

    float4 wr[KREG / 4];
    {
        const float4* Wg = reinterpret_cast<const float4*>(W_hh + (size_t)tid * HH);
#pragma unroll
        for (int i = 0; i < KREG / 4; i++) wr[i] = Wg[i];
    }
    for (int idx = tid; idx < KSMEM * GG; idx += 512) {
        int g2 = idx & (GG - 1);
        int ks = idx >> 9;
        Wt_s[idx] = W_hh[(size_t)g2 * HH + KREG + ks];
    }
    float c = 0.f;
    if (tid < HH) h_s[tid] = 0.f;
    __syncthreads();

    const float* xp = g_xproj + (size_t)b * TT * GG;
    const float4* h4s = reinterpret_cast<const float4*>(h_s);

    float xnext = xp[tid];                   // prefetch t=0

    for (int t = 0; t < TT; t++) {
        float acc = xnext;
        float acc2 = 0.f;
        if (t + 1 < TT) xnext = __ldg(xp + (t + 1) * GG + tid);  // hide latency

#pragma unroll
        for (int k4 = 0; k4 < KREG / 4; k4++) {
            float4 h4 = h4s[k4];
            acc  += wr[k4].x * h4.x;
            acc2 += wr[k4].y * h4.y;
            acc  += wr[k4].z * h4.z;
            acc2 += wr[k4].w * h4.w;
        }
#pragma unroll
        for (int k4 = KREG / 4; k4 < HH / 4; k4++) {
            float4 h4 = h4s[k4];
            int ks = (k4 - KREG / 4) * 4;
            acc  += Wt_s[(ks + 0) * GG + tid] * h4.x;
            acc2 += Wt_s[(ks + 1) * GG + tid] * h4.y;
            acc  += Wt_s[(ks + 2) * GG + tid] * h4.z;
            acc2 += Wt_s[(ks + 3) * GG + tid] * h4.w;
        }
        const float gv = acc + acc2;
        gates_s[tid] = (q == 2) ? tanh_fast(gv) : sigm_fast(gv);
        __syncthreads();

        if (tid < HH) {
            float ig = gates_s[tid];
            float fg = gates_s[HH + tid];
            float gg = gates_s[2 * HH + tid];
            float og = gates_s[3 * HH + tid];
            c = fg * c + ig * gg;
            float h = og * tanh_fast(c);
            h_s[tid] = h;
            __nv_bfloat16 hh = __float2bfloat16(h);
            float          hl = h - __bfloat162float(hh);
            size_t base = ((size_t)b * TT + t) * KSPLIT;
            g_hs_split[base + tid]       = hh;
            g_hs_split[base + 128 + tid] = hh;
            g_hs_split[base + 256 + tid] = __float2bfloat16(hl);
        }
        __syncthreads();
    }

    if (tid < HH && out_size >= (long long)FULL_OUT) {
        out[HF_OFF + (size_t)b * HH + tid] = h_s[tid];
        out[CF_OFF + (size_t)b * HH + tid] = c;
    }
}

// ---------------------------------------------------------------------------
// Kernel 2b: split W_fc into [hi|lo|hi] bf16 triple, zero-padded to VPAD rows
// ---------------------------------------------------------------------------
__global__ __launch_bounds__(256) void k_split_wfc(const float* __restrict__ W_fc)
{
    size_t i = (size_t)blockIdx.x * 256 + threadIdx.x;   // over VPAD*HH
    int v = (int)(i >> 7);
    int k = (int)(i & 127);
    float w = (v < VV) ? W_fc[i] : 0.f;
    __nv_bfloat16 hi = __float2bfloat16(w);
    float lo = w - __bfloat162float(hi);
    size_t base = (size_t)v * KSPLIT;
    g_wfc_split[base + k]       = hi;
    g_wfc_split[base + 128 + k] = __float2bfloat16(lo);
    g_wfc_split[base + 256 + k] = hi;
}

// ---------------------------------------------------------------------------
// Kernel 3: logits GEMM via mma.sync (bf16-split K=384, fp32 accum)
// 128x128 block tile, BK=64 chunks (6), 3-stage cp.async ring, 1 barrier/chunk.
// 8 warps as 2(m) x 4(n); warp tile 64x32 = 4x4 m16n8k16 tiles.
// ---------------------------------------------------------------------------
#define NK 6
#define STAGE_BYTES 32768          // A 16KB + B 16KB
#define SMEM3_BYTES (3 * STAGE_BYTES)

__device__ __forceinline__ void load_chunk(
    uint32_t smem_base, int stage,
    const __nv_bfloat16* __restrict__ asrc,   // + bt0*KSPLIT
    const __nv_bfloat16* __restrict__ bsrc,   // + v0*KSPLIT
    int kc, int tid)
{
    const int abuf = stage * STAGE_BYTES;
    const int bbuf = abuf + 16384;
    const int k0 = kc * 64;
#pragma unroll
    for (int it = 0; it < 4; it++) {
        int i = tid + it * 256;          // 0..1023
        int row = i >> 3;
        int j   = i & 7;
        uint32_t dst = smem_base + abuf + row * 128 + ((j ^ (row & 7)) << 4);
        cp16(dst, asrc + (size_t)row * KSPLIT + k0 + j * 8);
    }
#pragma unroll
    for (int it = 0; it < 4; it++) {
        int i = tid + it * 256;
        int row = i >> 3;
        int j   = i & 7;
        uint32_t dst = smem_base + bbuf + row * 128 + ((j ^ (row & 7)) << 4);
        cp16(dst, bsrc + (size_t)row * KSPLIT + k0 + j * 8);
    }
}

__global__ __launch_bounds__(256, 2) void k_logits_mma(
    const float* __restrict__ b_fc, float* __restrict__ out)
{
    extern __shared__ char smem3[];
    const uint32_t smem_base = smem_u32(smem3);
    const int tid = threadIdx.x;
    const int wid = tid >> 5;
    const int l   = tid & 31;
    const int v0  = blockIdx.x * 128;
    const int bt0 = blockIdx.y * 128;

    const __nv_bfloat16* asrc = g_hs_split + (size_t)bt0 * KSPLIT;
    const __nv_bfloat16* bsrc = g_wfc_split + (size_t)v0 * KSPLIT;

    const int wm = (wid >> 2) * 64;   // warp m offset (0/64)
    const int wn = (wid & 3) * 32;    // warp n offset (0..96)

    float c[4][4][4];
#pragma unroll
    for (int mi = 0; mi < 4; mi++)
#pragma unroll
        for (int nj = 0; nj < 4; nj++)
#pragma unroll
            for (int qq = 0; qq < 4; qq++) c[mi][nj][qq] = 0.f;

    const int lrow = l & 15;
    const int lsel = l >> 4;

    // prologue: 2 stages in flight
    load_chunk(smem_base, 0, asrc, bsrc, 0, tid);
    CP_COMMIT();
    load_chunk(smem_base, 1, asrc, bsrc, 1, tid);
    CP_COMMIT();

#pragma unroll
    for (int kc = 0; kc < NK; kc++) {
        if (kc < NK - 1) { CP_WAIT(1); } else { CP_WAIT(0); }
        __syncthreads();                       // chunk kc visible; prev compute done
        if (kc + 2 < NK) {
            load_chunk(smem_base, (kc + 2) % 3, asrc, bsrc, kc + 2, tid);
            CP_COMMIT();
        }

        const int abuf = (kc % 3) * STAGE_BYTES;
        const int bbuf = abuf + 16384;
#pragma unroll
        for (int k16 = 0; k16 < 4; k16++) {
            const int j = 2 * k16 + lsel;
            uint32_t a[4][4];
#pragma unroll
            for (int mi = 0; mi < 4; mi++) {
                int r = wm + mi * 16 + lrow;
                ldm4(a[mi], smem_base + abuf + r * 128 + ((j ^ (r & 7)) << 4));
            }
            uint32_t bfr[2][4];
#pragma unroll
            for (int njp = 0; njp < 2; njp++) {
                int r = wn + njp * 16 + lrow;
                ldm4(bfr[njp], smem_base + bbuf + r * 128 + ((j ^ (r & 7)) << 4));
            }
#pragma unroll
            for (int mi = 0; mi < 4; mi++) {
#pragma unroll
                for (int njp = 0; njp < 2; njp++) {
                    mma16816(c[mi][njp * 2 + 0], a[mi], bfr[njp][0], bfr[njp][2]);
                    mma16816(c[mi][njp * 2 + 1], a[mi], bfr[njp][1], bfr[njp][3]);
                }
            }
        }
    }

    // Epilogue: bias + guarded float2 stores
    const int g  = l >> 2;
    const int qq = l & 3;
    const int mB = bt0 + wm;
    const int nB = v0 + wn;

#pragma unroll
    for (int nj = 0; nj < 4; nj++) {
        const int v = nB + nj * 8 + 2 * qq;
        if (v >= VV) continue;
        const float2 bias = *reinterpret_cast<const float2*>(b_fc + v);
#pragma unroll
        for (int mi = 0; mi < 4; mi++) {
            const float* cc = c[mi][nj];
            const int r0 = mB + mi * 16 + g;
            float2 o0 = make_float2(cc[0] + bias.x, cc[1] + bias.y);
            float2 o1 = make_float2(cc[2] + bias.x, cc[3] + bias.y);
            *reinterpret_cast<float2*>(out + (size_t)r0 * VV + v)       = o0;
            *reinterpret_cast<float2*>(out + (size_t)(r0 + 8) * VV + v) = o1;
        }
    }
}

// ---------------------------------------------------------------------------
extern "C" void kernel_launch(void* const* d_in, const int* in_sizes, int n_in,
                              void* d_out, int out_size)
{
    const int*   x    = (const int*)  d_in[0];
    const float* emb  = (const float*)d_in[1];
    const float* W_ih = (const float*)d_in[2];
    const float* W_hh = (const float*)d_in[3];
    const float* b_ih = (const float*)d_in[4];
    const float* b_hh = (const float*)d_in[5];
    const float* W_fc = (const float*)d_in[6];
    const float* b_fc = (const float*)d_in[7];
    float* out = (float*)d_out;

    cudaFuncSetAttribute(k_lstm,       cudaFuncAttributeMaxDynamicSharedMemorySize, SMEM2_BYTES);
    cudaFuncSetAttribute(k_logits_mma, cudaFuncAttributeMaxDynamicSharedMemorySize, SMEM3_BYTES);

    // 1) embedding + input projection
    k_embed_proj<<<BT / 16, 512>>>(x, emb, W_ih, b_ih, b_hh);

    // 1b) W_fc bf16 split (independent of 1/2)
    k_split_wfc<<<(VPAD * HH) / 256, 256>>>(W_fc);

    // 2) recurrence (writes hs split + h_n/c_n tail of out)
    k_lstm<<<BB, 512, SMEM2_BYTES>>>(W_hh, out, (long long)out_size);

    // 3) logits GEMM on HMMA tensor cores
    dim3 g3(VPAD / 128, BT / 128);
    k_logits_mma<<<g3, 256, SMEM3_BYTES>>>(b_fc, out);
}